// round 7
// baseline (speedup 1.0000x reference)
#include <cuda_runtime.h>
#include <cstdint>

// GaussianTrans via mma.sync tf32 (arch-agnostic PTX path; tcgen05 is 'a'-gated).
//   outX[b,r,c,d] = sum_h sig(disX+attX) * V[b,r,h,d]   (pass X: write)
//   outY[b,r,c,d] = sum_w sig(disY+attY) * V[b,w,c,d]   (pass Y: accumulate)
// B=16, H=W=64, D=512. CTA = 64x128x64 GEMM tile, 4 warps each 64m x 32n.
// A smem: k-permuted [0,4,1,5,2,6,3,7] within each 8-group -> frag pair = LDS.64.
// V smem: (k,k+4) interleaved float2 pairs -> B frag pair = LDS.64.
// 5 software-pipelined launches: launch i = X(group i) + Y(group i-1).

#define SK  72    // As row stride (words): 72 % 32 == 8 -> conflict-free frags
#define SN2 132   // Vs pair-row stride (float2): conflict-free frag halves

static constexpr uint32_t SMEM_BYTES = (64 * SK + 32 * SN2 * 2) * 4;  // 52224

static __device__ __forceinline__ uint32_t tf32rn(float f) {
    uint32_t r;
    asm("cvt.rn.tf32.f32 %0, %1;" : "=r"(r) : "f"(f));
    return r;
}
static __device__ __forceinline__ float fast_sigmoid(float t) {
    return __fdividef(1.0f, 1.0f + __expf(-t));
}
static __device__ __forceinline__ void mma_tf32(float& c0, float& c1, float& c2,
                                                float& c3, uint32_t a0, uint32_t a1,
                                                uint32_t a2, uint32_t a3,
                                                uint32_t b0, uint32_t b1) {
    asm volatile(
        "mma.sync.aligned.m16n8k8.row.col.f32.tf32.tf32.f32 "
        "{%0,%1,%2,%3}, {%4,%5,%6,%7}, {%8,%9}, {%0,%1,%2,%3};"
        : "+f"(c0), "+f"(c1), "+f"(c2), "+f"(c3)
        : "r"(a0), "r"(a1), "r"(a2), "r"(a3), "r"(b0), "r"(b1));
}

__global__ __launch_bounds__(128, 4)
void gt_mma(const float* __restrict__ attX, const float* __restrict__ attY,
            const float* __restrict__ V, float* __restrict__ out,
            const float* __restrict__ shift, const float* __restrict__ bias,
            int bx0, int by0, int nx)
{
    extern __shared__ uint32_t smem[];
    uint32_t* As = smem;               // [64][SK], k-permuted tf32
    uint32_t* Vs = smem + 64 * SK;     // [32 pair-rows][SN2 float2]

    const int tid = threadIdx.x;
    const int dt    = blockIdx.x;          // 0..3 (d tile of 128)
    const int outer = blockIdx.y;          // r (pass X) or c (pass Y)
    const int z     = blockIdx.z;
    const bool passY = (z >= nx);
    const int b      = passY ? (by0 + z - nx) : (bx0 + z);
    const float* att = passY ? attY : attX;

    const float sh = shift[0], bi = bias[0];
    const int attBase = (b * 64 + outer) * 4096;
    const int off     = passY ? (b * 2097152 + outer * 512)
                              : ((b * 64 + outer) * 32768);
    const int vstride = passY ? 32768 : 512;
    const int dbase   = dt * 128;

    const int wid  = tid >> 5;
    const int lane = tid & 31;

    // --- A tile: sigmoid(dis+att) -> tf32, k-permuted within 8-groups ---
    #pragma unroll
    for (int j = 0; j < 8; ++j) {
        const int idx4 = tid + j * 128;          // 1024 float4 = 4096 elems
        const int m  = idx4 >> 4;
        const int k4 = (idx4 & 15) << 2;         // 4-aligned
        const float4 av = *reinterpret_cast<const float4*>(att + attBase + idx4 * 4);
        float d0 = (float)(k4 + 0 - m);
        float d1 = (float)(k4 + 1 - m);
        float d2 = (float)(k4 + 2 - m);
        float d3 = (float)(k4 + 3 - m);
        // position within 8-group: 2*(k&3) + ((k&4)?1:0)
        const int base = m * SK + (k4 & ~7) + ((k4 & 4) ? 1 : 0);
        As[base + 0] = tf32rn(fast_sigmoid(fmaf(-sh * d0, d0, av.x - bi)));
        As[base + 2] = tf32rn(fast_sigmoid(fmaf(-sh * d1, d1, av.y - bi)));
        As[base + 4] = tf32rn(fast_sigmoid(fmaf(-sh * d2, d2, av.z - bi)));
        As[base + 6] = tf32rn(fast_sigmoid(fmaf(-sh * d3, d3, av.w - bi)));
    }

    // --- V tile: rows (k, k+4) interleaved as float2 pairs; warp = one pair-row ---
    #pragma unroll
    for (int it = 0; it < 8; ++it) {
        const int pr = wid + it * 4;             // pair-row 0..31
        const int k8 = pr >> 2, t = pr & 3;
        const int k  = k8 * 8 + t;               // rows k and k+4
        const float* s0 = V + off + k * vstride + dbase + lane * 4;
        const float* s1 = s0 + 4 * vstride;
        const float4 v0 = *reinterpret_cast<const float4*>(s0);
        const float4 v1 = *reinterpret_cast<const float4*>(s1);
        uint32_t* dst = Vs + (pr * SN2 + lane * 4) * 2;
        uint4 w0, w1;
        w0.x = tf32rn(v0.x); w0.y = tf32rn(v1.x);
        w0.z = tf32rn(v0.y); w0.w = tf32rn(v1.y);
        w1.x = tf32rn(v0.z); w1.y = tf32rn(v1.z);
        w1.z = tf32rn(v0.w); w1.w = tf32rn(v1.w);
        *reinterpret_cast<uint4*>(dst)     = w0;
        *reinterpret_cast<uint4*>(dst + 4) = w1;
    }
    __syncthreads();

    // --- mma.sync m16n8k8 tf32: warp = 64m x 32n ---
    const int grp = lane >> 2;      // 0..7
    const int tig = lane & 3;       // 0..3
    const int n0  = wid * 32;

    float acc[4][4][4];
    #pragma unroll
    for (int mt = 0; mt < 4; ++mt)
        #pragma unroll
        for (int nt = 0; nt < 4; ++nt)
            #pragma unroll
            for (int q = 0; q < 4; ++q) acc[mt][nt][q] = 0.0f;

    #pragma unroll
    for (int k8 = 0; k8 < 8; ++k8) {
        const int kb = k8 * 8;
        uint32_t a[4][4];
        #pragma unroll
        for (int mt = 0; mt < 4; ++mt) {
            const int base = (mt * 16 + grp) * SK + kb + 2 * tig;
            const uint2 lo = *reinterpret_cast<const uint2*>(&As[base]);
            const uint2 hi = *reinterpret_cast<const uint2*>(&As[base + 8 * SK]);
            a[mt][0] = lo.x;   // (row,   col tig)
            a[mt][1] = hi.x;   // (row+8, col tig)
            a[mt][2] = lo.y;   // (row,   col tig+4)
            a[mt][3] = hi.y;   // (row+8, col tig+4)
        }
        #pragma unroll
        for (int nt = 0; nt < 4; ++nt) {
            const int nc = n0 + nt * 8 + grp;
            const uint2 bq = *reinterpret_cast<const uint2*>(
                &Vs[((k8 * 4 + tig) * SN2 + nc) * 2]);
            #pragma unroll
            for (int mt = 0; mt < 4; ++mt)
                mma_tf32(acc[mt][nt][0], acc[mt][nt][1],
                         acc[mt][nt][2], acc[mt][nt][3],
                         a[mt][0], a[mt][1], a[mt][2], a[mt][3], bq.x, bq.y);
        }
    }

    // --- epilogue: pass X writes; pass Y accumulates ---
    #pragma unroll
    for (int mt = 0; mt < 4; ++mt) {
        #pragma unroll
        for (int nt = 0; nt < 4; ++nt) {
            const int col  = dbase + n0 + nt * 8 + tig * 2;
            const int row0 = mt * 16 + grp;
            float* p0 = out + off + row0 * vstride + col;
            float* p1 = p0 + 8 * vstride;
            float2 w0 = make_float2(acc[mt][nt][0], acc[mt][nt][1]);
            float2 w1 = make_float2(acc[mt][nt][2], acc[mt][nt][3]);
            if (passY) {
                const float2 o0 = *reinterpret_cast<const float2*>(p0);
                const float2 o1 = *reinterpret_cast<const float2*>(p1);
                w0.x += o0.x; w0.y += o0.y;
                w1.x += o1.x; w1.y += o1.y;
            }
            *reinterpret_cast<float2*>(p0) = w0;
            *reinterpret_cast<float2*>(p1) = w1;
        }
    }
}

extern "C" void kernel_launch(void* const* d_in, const int* in_sizes, int n_in,
                              void* d_out, int out_size) {
    (void)in_sizes; (void)n_in; (void)out_size;
    // metadata order: x(unused), attentionXFull, attentionYFull, valueFull, shift, bias
    const float* attX  = (const float*)d_in[1];
    const float* attY  = (const float*)d_in[2];
    const float* V     = (const float*)d_in[3];
    const float* shift = (const float*)d_in[4];
    const float* bias  = (const float*)d_in[5];
    float* out = (float*)d_out;

    cudaFuncSetAttribute(gt_mma, cudaFuncAttributeMaxDynamicSharedMemorySize,
                         SMEM_BYTES);

    dim3 block(128);
    // Software pipeline across launches: launch i = X(group i) + Y(group i-1).
    // Y(b) reads outX(b) written by the PREVIOUS launch -> ordering by stream.
    // L0: X g0
    gt_mma<<<dim3(4, 64, 4), block, SMEM_BYTES>>>(attX, attY, V, out, shift, bias,
                                                  0, 0, 4);
    // L1..L3: X g(i) + Y g(i-1)
    for (int g = 1; g < 4; ++g) {
        gt_mma<<<dim3(4, 64, 8), block, SMEM_BYTES>>>(attX, attY, V, out, shift,
                                                      bias, g * 4, (g - 1) * 4, 4);
    }
    // L4: Y g3
    gt_mma<<<dim3(4, 64, 4), block, SMEM_BYTES>>>(attX, attY, V, out, shift, bias,
                                                  0, 12, 0);
}

// round 8
// speedup vs baseline: 1.2077x; 1.2077x over previous
#include <cuda_runtime.h>
#include <cstdint>

// GaussianTrans via mma.sync tf32 (arch-agnostic PTX path; tcgen05 is 'a'-gated).
//   outX[b,r,c,d] = sum_h sig(disX+attX) * V[b,r,h,d]   (pass X: write)
//   outY[b,r,c,d] = sum_w sig(disY+attY) * V[b,w,c,d]   (pass Y: accumulate)
// B=16, H=W=64, D=512. CTA = 64x128x64 GEMM tile, 4 warps each 64m x 32n.
// R5 structure + cp.async.cg for the V tile (raw fp32 bits; tf32 MMA truncates),
// issued before the A fill so LDGSTS overlaps att loads + sigmoid.
// X/Y launches interleaved per 4 batches so pass Y's V reads + out RMW hit L2.

#define SK 68    // As row stride (pad 4) -> conflict-free frag loads
#define SN 136   // Vs row stride (pad 8) -> conflict-free frag loads

static constexpr uint32_t SMEM_BYTES = (64 * SK + 64 * SN) * 4;  // 52224

static __device__ __forceinline__ uint32_t tf32rn(float f) {
    uint32_t r;
    asm("cvt.rn.tf32.f32 %0, %1;" : "=r"(r) : "f"(f));
    return r;
}
static __device__ __forceinline__ float fast_sigmoid(float t) {
    return __fdividef(1.0f, 1.0f + __expf(-t));
}
static __device__ __forceinline__ uint32_t smem_u32(const void* p) {
    uint32_t a;
    asm("{ .reg .u64 t; cvta.to.shared.u64 t, %1; cvt.u32.u64 %0, t; }"
        : "=r"(a) : "l"(p));
    return a;
}
static __device__ __forceinline__ void mma_tf32(float& c0, float& c1, float& c2,
                                                float& c3, uint32_t a0, uint32_t a1,
                                                uint32_t a2, uint32_t a3,
                                                uint32_t b0, uint32_t b1) {
    asm volatile(
        "mma.sync.aligned.m16n8k8.row.col.f32.tf32.tf32.f32 "
        "{%0,%1,%2,%3}, {%4,%5,%6,%7}, {%8,%9}, {%0,%1,%2,%3};"
        : "+f"(c0), "+f"(c1), "+f"(c2), "+f"(c3)
        : "r"(a0), "r"(a1), "r"(a2), "r"(a3), "r"(b0), "r"(b1));
}

template<bool PASSY>
__global__ __launch_bounds__(128, 4)
void gt_mma(const float* __restrict__ att, const float* __restrict__ V,
            float* __restrict__ out, const float* __restrict__ shift,
            const float* __restrict__ bias, int b0)
{
    extern __shared__ float smem[];
    float* As = smem;             // [64][SK], tf32-RN bit patterns
    float* Vs = smem + 64 * SK;   // [64][SN], raw fp32 (HW truncates to tf32)

    const int tid = threadIdx.x;
    const int dt    = blockIdx.x;          // 0..3 (d tile of 128)
    const int outer = blockIdx.y;          // r (pass X) or c (pass Y)
    const int b     = b0 + blockIdx.z;     // 4 batches per launch

    const float sh = shift[0], bi = bias[0];
    const int attBase = (b * 64 + outer) * 4096;
    const int off     = PASSY ? (b * 2097152 + outer * 512)
                              : ((b * 64 + outer) * 32768);
    const int vstride = PASSY ? 32768 : 512;
    const int dbase   = dt * 128;

    // --- V tile via cp.async.cg: 2048 x 16B, fire-and-forget, overlaps A fill ---
    {
        const uint32_t vsb = smem_u32(Vs);
        const float* srcBase = V + off + dbase;
        #pragma unroll
        for (int j = 0; j < 16; ++j) {
            const int idx4 = tid + j * 128;      // 2048 float4
            const int row  = idx4 >> 5;
            const int col  = (idx4 & 31) << 2;
            const float* src = srcBase + row * vstride + col;
            const uint32_t dst = vsb + (uint32_t)(row * SN + col) * 4u;
            asm volatile("cp.async.cg.shared.global [%0], [%1], 16;"
                         :: "r"(dst), "l"(src) : "memory");
        }
        asm volatile("cp.async.commit_group;" ::: "memory");
    }

    // --- A tile: sigmoid(dis + att) -> tf32-RN (overlaps the LDGSTS above) ---
    #pragma unroll
    for (int j = 0; j < 8; ++j) {
        const int idx4 = tid + j * 128;          // 1024 float4 = 4096 elems
        const int m  = idx4 >> 4;
        const int k4 = (idx4 & 15) << 2;
        const float4 av = *reinterpret_cast<const float4*>(att + attBase + idx4 * 4);
        float d0 = (float)(k4 + 0 - m);
        float d1 = (float)(k4 + 1 - m);
        float d2 = (float)(k4 + 2 - m);
        float d3 = (float)(k4 + 3 - m);
        uint4 sv;
        sv.x = tf32rn(fast_sigmoid(fmaf(-sh * d0, d0, av.x - bi)));
        sv.y = tf32rn(fast_sigmoid(fmaf(-sh * d1, d1, av.y - bi)));
        sv.z = tf32rn(fast_sigmoid(fmaf(-sh * d2, d2, av.z - bi)));
        sv.w = tf32rn(fast_sigmoid(fmaf(-sh * d3, d3, av.w - bi)));
        *reinterpret_cast<uint4*>(&As[m * SK + k4]) = sv;
    }

    asm volatile("cp.async.wait_group 0;" ::: "memory");
    __syncthreads();

    // --- mma.sync m16n8k8 tf32: warp = 64m x 32n (4 m-tiles x 4 n-tiles) ---
    const int wid  = tid >> 5;
    const int lane = tid & 31;
    const int grp  = lane >> 2;     // 0..7
    const int tig  = lane & 3;      // 0..3
    const int n0   = wid * 32;

    float acc[4][4][4];
    #pragma unroll
    for (int mt = 0; mt < 4; ++mt)
        #pragma unroll
        for (int nt = 0; nt < 4; ++nt)
            #pragma unroll
            for (int q = 0; q < 4; ++q) acc[mt][nt][q] = 0.0f;

    const uint32_t* Au = reinterpret_cast<const uint32_t*>(As);
    const uint32_t* Vu = reinterpret_cast<const uint32_t*>(Vs);

    #pragma unroll
    for (int k8 = 0; k8 < 8; ++k8) {
        const int kb = k8 * 8;
        uint32_t a[4][4];
        #pragma unroll
        for (int mt = 0; mt < 4; ++mt) {
            const int base = (mt * 16 + grp) * SK + kb + tig;
            a[mt][0] = Au[base];                 // (row,       col)
            a[mt][1] = Au[base + 8 * SK];        // (row+8,     col)
            a[mt][2] = Au[base + 4];             // (row,       col+4)
            a[mt][3] = Au[base + 8 * SK + 4];    // (row+8,     col+4)
        }
        #pragma unroll
        for (int nt = 0; nt < 4; ++nt) {
            const int nc = n0 + nt * 8 + grp;
            const uint32_t bq0 = Vu[(kb + tig) * SN + nc];
            const uint32_t bq1 = Vu[(kb + tig + 4) * SN + nc];
            #pragma unroll
            for (int mt = 0; mt < 4; ++mt)
                mma_tf32(acc[mt][nt][0], acc[mt][nt][1],
                         acc[mt][nt][2], acc[mt][nt][3],
                         a[mt][0], a[mt][1], a[mt][2], a[mt][3], bq0, bq1);
        }
    }

    // --- epilogue: c0,c1 -> (row, 2 cols); c2,c3 -> (row+8, 2 cols) ---
    #pragma unroll
    for (int mt = 0; mt < 4; ++mt) {
        #pragma unroll
        for (int nt = 0; nt < 4; ++nt) {
            const int col  = dbase + n0 + nt * 8 + tig * 2;
            const int row0 = mt * 16 + grp;
            float* p0 = out + off + row0 * vstride + col;
            float* p1 = p0 + 8 * vstride;
            float2 w0 = make_float2(acc[mt][nt][0], acc[mt][nt][1]);
            float2 w1 = make_float2(acc[mt][nt][2], acc[mt][nt][3]);
            if (PASSY) {
                const float2 o0 = *reinterpret_cast<const float2*>(p0);
                const float2 o1 = *reinterpret_cast<const float2*>(p1);
                w0.x += o0.x; w0.y += o0.y;
                w1.x += o1.x; w1.y += o1.y;
            }
            *reinterpret_cast<float2*>(p0) = w0;
            *reinterpret_cast<float2*>(p1) = w1;
        }
    }
}

extern "C" void kernel_launch(void* const* d_in, const int* in_sizes, int n_in,
                              void* d_out, int out_size) {
    (void)in_sizes; (void)n_in; (void)out_size;
    // metadata order: x(unused), attentionXFull, attentionYFull, valueFull, shift, bias
    const float* attX  = (const float*)d_in[1];
    const float* attY  = (const float*)d_in[2];
    const float* V     = (const float*)d_in[3];
    const float* shift = (const float*)d_in[4];
    const float* bias  = (const float*)d_in[5];
    float* out = (float*)d_out;

    cudaFuncSetAttribute(gt_mma<false>,
                         cudaFuncAttributeMaxDynamicSharedMemorySize, SMEM_BYTES);
    cudaFuncSetAttribute(gt_mma<true>,
                         cudaFuncAttributeMaxDynamicSharedMemorySize, SMEM_BYTES);

    dim3 grid(4, 64, 4);   // (d-tile, outer, 4 batches)
    dim3 block(128);
    // Interleave per 4 batches: pass Y hits V[b] and outX[b] in L2.
    for (int b0 = 0; b0 < 16; b0 += 4) {
        gt_mma<false><<<grid, block, SMEM_BYTES>>>(attX, V, out, shift, bias, b0);
        gt_mma<true ><<<grid, block, SMEM_BYTES>>>(attY, V, out, shift, bias, b0);
    }
}